// round 2
// baseline (speedup 1.0000x reference)
#include <cuda_runtime.h>
#include <stdint.h>

#define HW     1024
#define CH     256
#define BS     32
#define CAND   2048
#define NROWS  (BS*CAND)
#define MTILE  64
#define SROW   65          // padded row stride for [CH][SROW] activation tiles
#define KC     32          // k-chunk for weight staging
#define NBLK   (NROWS/MTILE)
#define SMEM_BYTES ((2*CH*SROW + 2*KC*CH)*4)

// ---------------- scratch (static device allocations are allowed) -----------
__device__ float g_t[BS*HW*CH];    // transposed gimage: [b][p][c], 128 MB
__device__ float g_wk[6*CH*CH];    // k-major weights:  [w][k][n], 1.5 MB

// ---------------- f32x2 helpers ---------------------------------------------
__device__ __forceinline__ uint64_t pack2(float lo, float hi) {
    uint64_t r; asm("mov.b64 %0, {%1,%2};" : "=l"(r) : "f"(lo), "f"(hi)); return r;
}
__device__ __forceinline__ void unpack2(uint64_t v, float& lo, float& hi) {
    asm("mov.b64 {%0,%1}, %2;" : "=f"(lo), "=f"(hi) : "l"(v));
}
#define FMA2(d, a, b) asm("fma.rn.f32x2 %0, %1, %2, %0;" : "+l"(d) : "l"(a), "l"(b))

// ---------------- cp.async helpers ------------------------------------------
__device__ __forceinline__ void cp16(void* sdst, const void* gsrc) {
    uint32_t s = (uint32_t)__cvta_generic_to_shared(sdst);
    asm volatile("cp.async.cg.shared.global [%0], [%1], 16;" :: "r"(s), "l"(gsrc));
}
__device__ __forceinline__ void cp_commit() { asm volatile("cp.async.commit_group;"); }
template <int N>
__device__ __forceinline__ void cp_wait() { asm volatile("cp.async.wait_group %0;" :: "n"(N)); }

// ---------------- kernel 1: transpose gimage [b][c][p] -> [b][p][c] ---------
__global__ void transpose_kernel(const float* __restrict__ g) {
    __shared__ float tile[32][33];
    int b  = blockIdx.z;
    int p0 = blockIdx.x * 32, c0 = blockIdx.y * 32;
    int tx = threadIdx.x, ty = threadIdx.y;          // 32 x 8
    const float* src = g   + (size_t)b * CH * HW;
    float*       dst = g_t + (size_t)b * HW * CH;
#pragma unroll
    for (int i = 0; i < 4; i++)
        tile[ty + i*8][tx] = src[(size_t)(c0 + ty + i*8) * HW + p0 + tx];
    __syncthreads();
#pragma unroll
    for (int i = 0; i < 4; i++)
        dst[(size_t)(p0 + ty + i*8) * CH + c0 + tx] = tile[tx][ty + i*8];
}

// ---------------- kernel 2: weight prep (center taps, k-major) --------------
// w0 = conv1 L0, w1 = conv2 L0, w2 = conv1 L1, w3 = conv2 L1, w4 = mlp1, w5 = mlp2
__global__ void prep_kernel(const float* __restrict__ c1, const float* __restrict__ c2,
                            const float* __restrict__ m1, const float* __restrict__ m2) {
    int gid = blockIdx.x * 256 + threadIdx.x;        // 0 .. 6*65536-1
    int w = gid >> 16;
    int e = gid & 65535;
    int k = e >> 8, n = e & 255;
    float v;
    if (w < 4) {
        const float* src = (w & 1) ? c2 : c1;        // [2][256][256][3][3]
        int layer = w >> 1;
        v = src[(size_t)layer * CH * CH * 9 + (size_t)(n * CH + k) * 9 + 4];
    } else {
        const float* src = (w == 4) ? m1 : m2;       // [256][256]
        v = src[n * CH + k];
    }
    g_wk[(size_t)w * 65536 + e] = v;                 // [k][n]
}

// ---------------- fused main kernel -----------------------------------------
// Tile GEMM: out[m][n] = sum_k src[k][m] * W[k][n], M=64, N=256, K=256.
// Thread (tm,tn): rows tm*4..tm*4+3, col pairs 2*(tn+16j), j=0..7.
__device__ __forceinline__ void gemm256(const float* __restrict__ src,
                                        float* __restrict__ wbuf,
                                        const float* __restrict__ wg,
                                        uint64_t acc[4][8], int tid) {
    const int tm = tid >> 4, tn = tid & 15;
#pragma unroll
    for (int r = 0; r < 4; r++)
#pragma unroll
        for (int j = 0; j < 8; j++) acc[r][j] = 0ull;

    // prefetch chunk 0
    {
        const float* gsrc = wg;
#pragma unroll
        for (int i = 0; i < 8; i++)
            cp16(wbuf + (i * 256 + tid) * 4, gsrc + (i * 256 + tid) * 4);
        cp_commit();
    }
#pragma unroll 1
    for (int ci = 0; ci < 8; ci++) {
        if (ci < 7) {
            const float* gsrc = wg + (size_t)(ci + 1) * KC * CH;
            float* sdst = wbuf + ((ci + 1) & 1) * KC * CH;
#pragma unroll
            for (int i = 0; i < 8; i++)
                cp16(sdst + (i * 256 + tid) * 4, gsrc + (i * 256 + tid) * 4);
            cp_commit();
            cp_wait<1>();
        } else {
            cp_wait<0>();
        }
        __syncthreads();
        const float* wb = wbuf + (ci & 1) * KC * CH;
        const float* sx = src + ci * KC * SROW + tm * 4;
#pragma unroll 8
        for (int kk = 0; kk < KC; kk++) {
            float x0 = sx[kk * SROW + 0], x1 = sx[kk * SROW + 1];
            float x2 = sx[kk * SROW + 2], x3 = sx[kk * SROW + 3];
            uint64_t xp0 = pack2(x0, x0), xp1 = pack2(x1, x1);
            uint64_t xp2 = pack2(x2, x2), xp3 = pack2(x3, x3);
            const float* wr = wb + kk * CH;
#pragma unroll
            for (int j = 0; j < 8; j++) {
                uint64_t wv = *reinterpret_cast<const uint64_t*>(wr + 2 * (tn + 16 * j));
                FMA2(acc[0][j], xp0, wv);
                FMA2(acc[1][j], xp1, wv);
                FMA2(acc[2][j], xp2, wv);
                FMA2(acc[3][j], xp3, wv);
            }
        }
        __syncthreads();   // all reads of wbuf[ci&1] done before next refill
    }
}

// GroupNorm(32 groups of 8) + SiLU over the 64x256 tile (k-major layout).
__device__ __forceinline__ void gn_silu(const float* __restrict__ src,
                                        float* __restrict__ dst,
                                        const float* __restrict__ gw,
                                        const float* __restrict__ gb, int tid) {
    __syncthreads();
#pragma unroll 1
    for (int it = 0; it < 8; it++) {
        int t = tid + 256 * it;           // (row, group) task, 2048 total
        int m = t & 63, g = t >> 6;
        float v[8]; float s = 0.f;
#pragma unroll
        for (int c = 0; c < 8; c++) { v[c] = src[(g * 8 + c) * SROW + m]; s += v[c]; }
        float mean = s * 0.125f;
        float var = 0.f;
#pragma unroll
        for (int c = 0; c < 8; c++) { float d = v[c] - mean; var += d * d; }
        var *= 0.125f;
        float rs = rsqrtf(var + 1e-5f);
#pragma unroll
        for (int c = 0; c < 8; c++) {
            float xn = (v[c] - mean) * rs * gw[g * 8 + c] + gb[g * 8 + c];
            dst[(g * 8 + c) * SROW + m] = xn * (1.f / (1.f + __expf(-xn)));
        }
    }
    __syncthreads();
}

__global__ __launch_bounds__(256) void main_kernel(
    const int*   __restrict__ pts,
    const float* __restrict__ gn1w, const float* __restrict__ gn1b,
    const float* __restrict__ c1b,
    const float* __restrict__ gn2w, const float* __restrict__ gn2b,
    const float* __restrict__ c2b,
    const float* __restrict__ clsw, const float* __restrict__ clsb,
    const float* __restrict__ mb1,  const float* __restrict__ mb2,
    const float* __restrict__ mw3,  const float* __restrict__ mb3,
    float* __restrict__ out) {
    extern __shared__ float smem[];
    float* xs   = smem;                   // [CH][SROW] current x (residual)
    float* ts   = smem + CH * SROW;       // [CH][SROW] temp activations
    float* wbuf = smem + 2 * CH * SROW;   // [2][KC][CH] weight chunks
    __shared__ int lins[64];

    int tid = threadIdx.x;
    int tm = tid >> 4, tn = tid & 15;
    int row_base = blockIdx.x * MTILE;

    // gather offsets: lin = (pts_y/8)*32 + pts_x/8
    if (tid < 64) {
        int r  = row_base + tid;
        int p0 = pts[r * 2 + 0], p1 = pts[r * 2 + 1];
        int b  = r >> 11;
        lins[tid] = (b * HW + ((p0 >> 3) * 32 + (p1 >> 3))) * CH;
    }
    __syncthreads();
    // gather rows (thread = channel; coalesced reads from transposed image)
#pragma unroll 4
    for (int m = 0; m < MTILE; m++)
        xs[tid * SROW + m] = g_t[lins[m] + tid];
    __syncthreads();

    uint64_t acc[4][8];

    // ---- two residual blocks ----
#pragma unroll 1
    for (int L = 0; L < 2; L++) {
        gn_silu(xs, ts, gn1w + L * CH, gn1b + L * CH, tid);
        gemm256(ts, wbuf, g_wk + (size_t)(L * 2 + 0) * 65536, acc, tid);
#pragma unroll
        for (int r = 0; r < 4; r++) {
            int m = tm * 4 + r;
#pragma unroll
            for (int j = 0; j < 8; j++) {
                int n = 2 * (tn + 16 * j);
                float f0, f1; unpack2(acc[r][j], f0, f1);
                ts[n * SROW + m]       = f0 + c1b[L * CH + n];
                ts[(n + 1) * SROW + m] = f1 + c1b[L * CH + n + 1];
            }
        }
        gn_silu(ts, ts, gn2w + L * CH, gn2b + L * CH, tid);
        gemm256(ts, wbuf, g_wk + (size_t)(L * 2 + 1) * 65536, acc, tid);
#pragma unroll
        for (int r = 0; r < 4; r++) {
            int m = tm * 4 + r;
#pragma unroll
            for (int j = 0; j < 8; j++) {
                int n = 2 * (tn + 16 * j);
                float f0, f1; unpack2(acc[r][j], f0, f1);
                xs[n * SROW + m]       += f0 + c2b[L * CH + n];
                xs[(n + 1) * SROW + m] += f1 + c2b[L * CH + n + 1];
            }
        }
        __syncthreads();
    }

    // ---- MLP layer 1: ts = relu(xs @ w4 + b1) ----
    gemm256(xs, wbuf, g_wk + (size_t)4 * 65536, acc, tid);
#pragma unroll
    for (int r = 0; r < 4; r++) {
        int m = tm * 4 + r;
#pragma unroll
        for (int j = 0; j < 8; j++) {
            int n = 2 * (tn + 16 * j);
            float f0, f1; unpack2(acc[r][j], f0, f1);
            ts[n * SROW + m]       = fmaxf(f0 + mb1[n], 0.f);
            ts[(n + 1) * SROW + m] = fmaxf(f1 + mb1[n + 1], 0.f);
        }
    }
    __syncthreads();
    // ---- MLP layer 2: ts = relu(ts @ w5 + b2) ----
    gemm256(ts, wbuf, g_wk + (size_t)5 * 65536, acc, tid);
#pragma unroll
    for (int r = 0; r < 4; r++) {
        int m = tm * 4 + r;
#pragma unroll
        for (int j = 0; j < 8; j++) {
            int n = 2 * (tn + 16 * j);
            float f0, f1; unpack2(acc[r][j], f0, f1);
            ts[n * SROW + m]       = fmaxf(f0 + mb2[n], 0.f);
            ts[(n + 1) * SROW + m] = fmaxf(f1 + mb2[n + 1], 0.f);
        }
    }
    __syncthreads();

    // ---- heads: cls (from xs) and box (from ts) ----
    int m = tid & 63, slot = tid >> 6;   // 4 threads per row
    float a3 = 0.f;
#pragma unroll 8
    for (int k = 0; k < CH; k++) a3 += ts[k * SROW + m] * mw3[slot * CH + k];
    a3 += mb3[slot];
    out[131072 + (size_t)(row_base + m) * 4 + slot] = 1.f / (1.f + __expf(-a3));
    if (slot < 2) {
        float al = 0.f;
#pragma unroll 8
        for (int k = 0; k < CH; k++) al += xs[k * SROW + m] * clsw[slot * CH + k];
        out[(size_t)(row_base + m) * 2 + slot] = al + clsb[slot];
    }
}

// ---------------- launch ------------------------------------------------------
extern "C" void kernel_launch(void* const* d_in, const int* in_sizes, int n_in,
                              void* d_out, int out_size) {
    const float* gimage = (const float*)d_in[0];
    const int*   pts    = (const int*)  d_in[1];
    const float* gn1w   = (const float*)d_in[2];
    const float* gn1b   = (const float*)d_in[3];
    const float* c1w    = (const float*)d_in[4];
    const float* c1b    = (const float*)d_in[5];
    const float* gn2w   = (const float*)d_in[6];
    const float* gn2b   = (const float*)d_in[7];
    const float* c2w    = (const float*)d_in[8];
    const float* c2b    = (const float*)d_in[9];
    const float* clsw   = (const float*)d_in[10];
    const float* clsb   = (const float*)d_in[11];
    const float* mw1    = (const float*)d_in[12];
    const float* mb1    = (const float*)d_in[13];
    const float* mw2    = (const float*)d_in[14];
    const float* mb2    = (const float*)d_in[15];
    const float* mw3    = (const float*)d_in[16];
    const float* mb3    = (const float*)d_in[17];
    float* out = (float*)d_out;

    cudaFuncSetAttribute(main_kernel, cudaFuncAttributeMaxDynamicSharedMemorySize,
                         SMEM_BYTES);

    dim3 tgrid(HW / 32, CH / 32, BS), tblk(32, 8);
    transpose_kernel<<<tgrid, tblk>>>(gimage);
    prep_kernel<<<(6 * 65536) / 256, 256>>>(c1w, c2w, mw1, mw2);
    main_kernel<<<NBLK, 256, SMEM_BYTES>>>(pts, gn1w, gn1b, c1b, gn2w, gn2b, c2b,
                                           clsw, clsb, mb1, mb2, mw3, mb3, out);
}

// round 3
// speedup vs baseline: 1.0014x; 1.0014x over previous
#include <cuda_runtime.h>
#include <stdint.h>

#define HW     1024
#define CH     256
#define BS     32
#define CAND   2048
#define NROWS  (BS*CAND)
#define MTILE  64
#define SROW   65          // padded row stride for [CH][SROW] activation tiles
#define KC     32          // k-chunk for weight staging
#define NBLK   (NROWS/MTILE)
#define SMEM_BYTES ((2*CH*SROW + 2*KC*CH)*4)

// ---------------- scratch (static device allocations are allowed) -----------
__device__ float g_t[BS*HW*CH];    // transposed gimage: [b][p][c], 128 MB
__device__ float g_wk[6*CH*CH];    // k-major weights:  [w][k][n], 1.5 MB

// ---------------- f32x2 helpers ---------------------------------------------
__device__ __forceinline__ uint64_t pack2(float lo, float hi) {
    uint64_t r; asm("mov.b64 %0, {%1,%2};" : "=l"(r) : "f"(lo), "f"(hi)); return r;
}
__device__ __forceinline__ void unpack2(uint64_t v, float& lo, float& hi) {
    asm("mov.b64 {%0,%1}, %2;" : "=f"(lo), "=f"(hi) : "l"(v));
}
#define FMA2(d, a, b) asm("fma.rn.f32x2 %0, %1, %2, %0;" : "+l"(d) : "l"(a), "l"(b))

// ---------------- cp.async helpers ------------------------------------------
__device__ __forceinline__ void cp16(void* sdst, const void* gsrc) {
    uint32_t s = (uint32_t)__cvta_generic_to_shared(sdst);
    asm volatile("cp.async.cg.shared.global [%0], [%1], 16;" :: "r"(s), "l"(gsrc));
}
__device__ __forceinline__ void cp_commit() { asm volatile("cp.async.commit_group;"); }
template <int N>
__device__ __forceinline__ void cp_wait() { asm volatile("cp.async.wait_group %0;" :: "n"(N)); }

// ---------------- kernel 1: transpose gimage [b][c][p] -> [b][p][c] ---------
__global__ void transpose_kernel(const float* __restrict__ g) {
    __shared__ float tile[32][33];
    int b  = blockIdx.z;
    int p0 = blockIdx.x * 32, c0 = blockIdx.y * 32;
    int tx = threadIdx.x, ty = threadIdx.y;          // 32 x 8
    const float* src = g   + (size_t)b * CH * HW;
    float*       dst = g_t + (size_t)b * HW * CH;
#pragma unroll
    for (int i = 0; i < 4; i++)
        tile[ty + i*8][tx] = src[(size_t)(c0 + ty + i*8) * HW + p0 + tx];
    __syncthreads();
#pragma unroll
    for (int i = 0; i < 4; i++)
        dst[(size_t)(p0 + ty + i*8) * CH + c0 + tx] = tile[tx][ty + i*8];
}

// ---------------- kernel 2: weight prep (center taps, k-major) --------------
// w0 = conv1 L0, w1 = conv2 L0, w2 = conv1 L1, w3 = conv2 L1, w4 = mlp1, w5 = mlp2
__global__ void prep_kernel(const float* __restrict__ c1, const float* __restrict__ c2,
                            const float* __restrict__ m1, const float* __restrict__ m2) {
    int gid = blockIdx.x * 256 + threadIdx.x;        // 0 .. 6*65536-1
    int w = gid >> 16;
    int e = gid & 65535;
    int k = e >> 8, n = e & 255;
    float v;
    if (w < 4) {
        const float* src = (w & 1) ? c2 : c1;        // [2][256][256][3][3]
        int layer = w >> 1;
        v = src[(size_t)layer * CH * CH * 9 + (size_t)(n * CH + k) * 9 + 4];
    } else {
        const float* src = (w == 4) ? m1 : m2;       // [256][256]
        v = src[n * CH + k];
    }
    g_wk[(size_t)w * 65536 + e] = v;                 // [k][n]
}

// ---------------- fused main kernel -----------------------------------------
// Tile GEMM: out[m][n] = sum_k src[k][m] * W[k][n], M=64, N=256, K=256.
// Thread (tm,tn): rows tm*4..tm*4+3, col pairs 2*(tn+16j), j=0..7.
__device__ __forceinline__ void gemm256(const float* __restrict__ src,
                                        float* __restrict__ wbuf,
                                        const float* __restrict__ wg,
                                        uint64_t acc[4][8], int tid) {
    const int tm = tid >> 4, tn = tid & 15;
#pragma unroll
    for (int r = 0; r < 4; r++)
#pragma unroll
        for (int j = 0; j < 8; j++) acc[r][j] = 0ull;

    // prefetch chunk 0
    {
        const float* gsrc = wg;
#pragma unroll
        for (int i = 0; i < 8; i++)
            cp16(wbuf + (i * 256 + tid) * 4, gsrc + (i * 256 + tid) * 4);
        cp_commit();
    }
#pragma unroll 1
    for (int ci = 0; ci < 8; ci++) {
        if (ci < 7) {
            const float* gsrc = wg + (size_t)(ci + 1) * KC * CH;
            float* sdst = wbuf + ((ci + 1) & 1) * KC * CH;
#pragma unroll
            for (int i = 0; i < 8; i++)
                cp16(sdst + (i * 256 + tid) * 4, gsrc + (i * 256 + tid) * 4);
            cp_commit();
            cp_wait<1>();
        } else {
            cp_wait<0>();
        }
        __syncthreads();
        const float* wb = wbuf + (ci & 1) * KC * CH;
        const float* sx = src + ci * KC * SROW + tm * 4;
#pragma unroll 8
        for (int kk = 0; kk < KC; kk++) {
            float x0 = sx[kk * SROW + 0], x1 = sx[kk * SROW + 1];
            float x2 = sx[kk * SROW + 2], x3 = sx[kk * SROW + 3];
            uint64_t xp0 = pack2(x0, x0), xp1 = pack2(x1, x1);
            uint64_t xp2 = pack2(x2, x2), xp3 = pack2(x3, x3);
            const float* wr = wb + kk * CH;
#pragma unroll
            for (int j = 0; j < 8; j++) {
                uint64_t wv = *reinterpret_cast<const uint64_t*>(wr + 2 * (tn + 16 * j));
                FMA2(acc[0][j], xp0, wv);
                FMA2(acc[1][j], xp1, wv);
                FMA2(acc[2][j], xp2, wv);
                FMA2(acc[3][j], xp3, wv);
            }
        }
        __syncthreads();   // all reads of wbuf[ci&1] done before next refill
    }
}

// GroupNorm(32 groups of 8) + SiLU over the 64x256 tile (k-major layout).
__device__ __forceinline__ void gn_silu(const float* __restrict__ src,
                                        float* __restrict__ dst,
                                        const float* __restrict__ gw,
                                        const float* __restrict__ gb, int tid) {
    __syncthreads();
#pragma unroll 1
    for (int it = 0; it < 8; it++) {
        int t = tid + 256 * it;           // (row, group) task, 2048 total
        int m = t & 63, g = t >> 6;
        float v[8]; float s = 0.f;
#pragma unroll
        for (int c = 0; c < 8; c++) { v[c] = src[(g * 8 + c) * SROW + m]; s += v[c]; }
        float mean = s * 0.125f;
        float var = 0.f;
#pragma unroll
        for (int c = 0; c < 8; c++) { float d = v[c] - mean; var += d * d; }
        var *= 0.125f;
        float rs = rsqrtf(var + 1e-5f);
#pragma unroll
        for (int c = 0; c < 8; c++) {
            float xn = (v[c] - mean) * rs * gw[g * 8 + c] + gb[g * 8 + c];
            dst[(g * 8 + c) * SROW + m] = xn * (1.f / (1.f + __expf(-xn)));
        }
    }
    __syncthreads();
}

__global__ __launch_bounds__(256) void main_kernel(
    const int*   __restrict__ pts,
    const float* __restrict__ gn1w, const float* __restrict__ gn1b,
    const float* __restrict__ c1b,
    const float* __restrict__ gn2w, const float* __restrict__ gn2b,
    const float* __restrict__ c2b,
    const float* __restrict__ clsw, const float* __restrict__ clsb,
    const float* __restrict__ mb1,  const float* __restrict__ mb2,
    const float* __restrict__ mw3,  const float* __restrict__ mb3,
    float* __restrict__ out) {
    extern __shared__ float smem[];
    float* xs   = smem;                   // [CH][SROW] current x (residual)
    float* ts   = smem + CH * SROW;       // [CH][SROW] temp activations
    float* wbuf = smem + 2 * CH * SROW;   // [2][KC][CH] weight chunks
    __shared__ int lins[64];

    int tid = threadIdx.x;
    int tm = tid >> 4, tn = tid & 15;
    int row_base = blockIdx.x * MTILE;

    // gather offsets: lin = (pts_y/8)*32 + pts_x/8
    if (tid < 64) {
        int r  = row_base + tid;
        int p0 = pts[r * 2 + 0], p1 = pts[r * 2 + 1];
        int b  = r >> 11;
        lins[tid] = (b * HW + ((p0 >> 3) * 32 + (p1 >> 3))) * CH;
    }
    __syncthreads();
    // gather rows (thread = channel; coalesced reads from transposed image)
#pragma unroll 4
    for (int m = 0; m < MTILE; m++)
        xs[tid * SROW + m] = g_t[lins[m] + tid];
    __syncthreads();

    uint64_t acc[4][8];

    // ---- two residual blocks ----
#pragma unroll 1
    for (int L = 0; L < 2; L++) {
        gn_silu(xs, ts, gn1w + L * CH, gn1b + L * CH, tid);
        gemm256(ts, wbuf, g_wk + (size_t)(L * 2 + 0) * 65536, acc, tid);
#pragma unroll
        for (int r = 0; r < 4; r++) {
            int m = tm * 4 + r;
#pragma unroll
            for (int j = 0; j < 8; j++) {
                int n = 2 * (tn + 16 * j);
                float f0, f1; unpack2(acc[r][j], f0, f1);
                ts[n * SROW + m]       = f0 + c1b[L * CH + n];
                ts[(n + 1) * SROW + m] = f1 + c1b[L * CH + n + 1];
            }
        }
        gn_silu(ts, ts, gn2w + L * CH, gn2b + L * CH, tid);
        gemm256(ts, wbuf, g_wk + (size_t)(L * 2 + 1) * 65536, acc, tid);
#pragma unroll
        for (int r = 0; r < 4; r++) {
            int m = tm * 4 + r;
#pragma unroll
            for (int j = 0; j < 8; j++) {
                int n = 2 * (tn + 16 * j);
                float f0, f1; unpack2(acc[r][j], f0, f1);
                xs[n * SROW + m]       += f0 + c2b[L * CH + n];
                xs[(n + 1) * SROW + m] += f1 + c2b[L * CH + n + 1];
            }
        }
        __syncthreads();
    }

    // ---- MLP layer 1: ts = relu(xs @ w4 + b1) ----
    gemm256(xs, wbuf, g_wk + (size_t)4 * 65536, acc, tid);
#pragma unroll
    for (int r = 0; r < 4; r++) {
        int m = tm * 4 + r;
#pragma unroll
        for (int j = 0; j < 8; j++) {
            int n = 2 * (tn + 16 * j);
            float f0, f1; unpack2(acc[r][j], f0, f1);
            ts[n * SROW + m]       = fmaxf(f0 + mb1[n], 0.f);
            ts[(n + 1) * SROW + m] = fmaxf(f1 + mb1[n + 1], 0.f);
        }
    }
    __syncthreads();
    // ---- MLP layer 2: ts = relu(ts @ w5 + b2) ----
    gemm256(ts, wbuf, g_wk + (size_t)5 * 65536, acc, tid);
#pragma unroll
    for (int r = 0; r < 4; r++) {
        int m = tm * 4 + r;
#pragma unroll
        for (int j = 0; j < 8; j++) {
            int n = 2 * (tn + 16 * j);
            float f0, f1; unpack2(acc[r][j], f0, f1);
            ts[n * SROW + m]       = fmaxf(f0 + mb2[n], 0.f);
            ts[(n + 1) * SROW + m] = fmaxf(f1 + mb2[n + 1], 0.f);
        }
    }
    __syncthreads();

    // ---- heads: cls (from xs) and box (from ts) ----
    int m = tid & 63, slot = tid >> 6;   // 4 threads per row
    float a3 = 0.f;
#pragma unroll 8
    for (int k = 0; k < CH; k++) a3 += ts[k * SROW + m] * mw3[slot * CH + k];
    a3 += mb3[slot];
    out[131072 + (size_t)(row_base + m) * 4 + slot] = 1.f / (1.f + __expf(-a3));
    if (slot < 2) {
        float al = 0.f;
#pragma unroll 8
        for (int k = 0; k < CH; k++) al += xs[k * SROW + m] * clsw[slot * CH + k];
        out[(size_t)(row_base + m) * 2 + slot] = al + clsb[slot];
    }
}

// ---------------- launch ------------------------------------------------------
extern "C" void kernel_launch(void* const* d_in, const int* in_sizes, int n_in,
                              void* d_out, int out_size) {
    const float* gimage = (const float*)d_in[0];
    const int*   pts    = (const int*)  d_in[1];
    const float* gn1w   = (const float*)d_in[2];
    const float* gn1b   = (const float*)d_in[3];
    const float* c1w    = (const float*)d_in[4];
    const float* c1b    = (const float*)d_in[5];
    const float* gn2w   = (const float*)d_in[6];
    const float* gn2b   = (const float*)d_in[7];
    const float* c2w    = (const float*)d_in[8];
    const float* c2b    = (const float*)d_in[9];
    const float* clsw   = (const float*)d_in[10];
    const float* clsb   = (const float*)d_in[11];
    const float* mw1    = (const float*)d_in[12];
    const float* mb1    = (const float*)d_in[13];
    const float* mw2    = (const float*)d_in[14];
    const float* mb2    = (const float*)d_in[15];
    const float* mw3    = (const float*)d_in[16];
    const float* mb3    = (const float*)d_in[17];
    float* out = (float*)d_out;

    cudaFuncSetAttribute(main_kernel, cudaFuncAttributeMaxDynamicSharedMemorySize,
                         SMEM_BYTES);

    dim3 tgrid(HW / 32, CH / 32, BS), tblk(32, 8);
    transpose_kernel<<<tgrid, tblk>>>(gimage);
    prep_kernel<<<(6 * 65536) / 256, 256>>>(c1w, c2w, mw1, mw2);
    main_kernel<<<NBLK, 256, SMEM_BYTES>>>(pts, gn1w, gn1b, c1b, gn2w, gn2b, c2b,
                                           clsw, clsb, mb1, mb2, mw3, mb3, out);
}